// round 1
// baseline (speedup 1.0000x reference)
#include <cuda_runtime.h>

// ---------------- problem constants ----------------
#define BB   256      // batch
#define DD   200      // embedding dim
#define ODIM 100      // ontology dim
#define NO   5000     // ontology rows
#define NL   50000    // locations
#define FCL  78       // conv feature length (2*39)
#define KD   80       // padded K
#define NLP  50048    // NL padded to GEMM tile multiple (391*128)

// ---------------- device scratch (zero-initialized .bss) ----------------
__device__ float g_s [BB * ODIM];     // typeSub + subRel
__device__ float g_qT[KD * BB];       // q transposed: [k][b]
__device__ float g_c [BB];            // p . fc_b
__device__ float g_FT[KD * NLP];      // F transposed: [k][n], tail n>=NL stays 0

// ============================================================
// K0: all per-batch work. 1 block per batch element.
//  subRel, s, tt, 4x (conv + FC), p, q = p@fc_W, c = p.fc_b
// ============================================================
__global__ void k0_batch(const int* __restrict__ rel_idx,
                         const int* __restrict__ rel2_idx,
                         const int* __restrict__ user_idx,
                         const int* __restrict__ hour_idx,
                         const int* __restrict__ day_idx,
                         const int* __restrict__ type_idx,
                         const float* __restrict__ entity,
                         const float* __restrict__ ont,
                         const float* __restrict__ relation,
                         const float* __restrict__ proj_W,
                         const float* __restrict__ proj_b,
                         const float* __restrict__ pR_W,
                         const float* __restrict__ pR_b,
                         const float* __restrict__ fc2_W,
                         const float* __restrict__ fc2_b,
                         const float* __restrict__ fc_W,
                         const float* __restrict__ fc_b)
{
    const int b   = blockIdx.x;
    const int tid = threadIdx.x;

    __shared__ float sm_e[DD];      // staging vector (rel2 emb, then conv inputs)
    __shared__ float sm_ts[ODIM];   // typeSub
    __shared__ float sm_tt[DD];     // relu(typeSub @ proj_W.T + proj_b)
    __shared__ float sm_p[DD];      // running product
    __shared__ float sm_y[FCL];     // conv output
    __shared__ float sm_k[20];      // conv kernel
    __shared__ float sm_red[8];

    const int i_type = type_idx[b];
    if (tid < ODIM) sm_ts[tid] = ont[i_type * ODIM + tid];
    const int i_r2 = rel2_idx[b];
    if (tid < DD)   sm_e[tid] = relation[i_r2 * DD + tid];
    __syncthreads();

    // subRel + s  (threads 0..99)
    if (tid < ODIM) {
        float acc = pR_b[tid];
        const float* w = pR_W + tid * DD;
        #pragma unroll 8
        for (int d = 0; d < DD; d++) acc = fmaf(sm_e[d], w[d], acc);
        g_s[b * ODIM + tid] = sm_ts[tid] + fmaxf(acc, 0.f);
    }
    // tt = relu(typeSub @ proj_W.T + proj_b)  (threads 0..199)
    if (tid < DD) {
        float acc = proj_b[tid];
        const float* w = proj_W + tid * ODIM;
        #pragma unroll 10
        for (int i = 0; i < ODIM; i++) acc = fmaf(sm_ts[i], w[i], acc);
        sm_tt[tid] = fmaxf(acc, 0.f);
    }
    const int i_rel = rel_idx[b];
    if (tid < DD) sm_p[tid] = relation[i_rel * DD + tid];

    // four convolution stages: user(pos1), day(pos2), hour(pos3), tt(pos5)
    int idxs[4];
    idxs[0] = user_idx[b]; idxs[1] = day_idx[b]; idxs[2] = hour_idx[b]; idxs[3] = -1;
    const int poss[4] = {1, 2, 3, 5};

    for (int s = 0; s < 4; s++) {
        __syncthreads();   // protect sm_e / sm_y consumers of previous stage
        if (tid < DD) sm_e[tid] = (idxs[s] >= 0) ? entity[(long)idxs[s] * DD + tid]
                                                 : sm_tt[tid];
        if (tid < 20) sm_k[tid] = fc2_W[tid * 6 + poss[s]] + fc2_b[tid];
        __syncthreads();
        if (tid < FCL) {
            const int ch = tid / 39, w = tid % 39;
            float acc = 0.f;
            #pragma unroll
            for (int j = 0; j < 10; j++)
                acc = fmaf(sm_e[w * 5 + j], sm_k[ch * 10 + j], acc);
            sm_y[tid] = acc;
        }
        __syncthreads();
        if (tid < DD) {
            float acc = fc_b[tid];
            const float* w = fc_W + tid * FCL;
            #pragma unroll 6
            for (int f = 0; f < FCL; f++) acc = fmaf(sm_y[f], w[f], acc);
            sm_p[tid] *= acc;
        }
    }
    __syncthreads();

    // q[f] = sum_d p[d] * fc_W[d][f]   (stored transposed)
    if (tid < FCL) {
        float acc = 0.f;
        #pragma unroll 8
        for (int d = 0; d < DD; d++) acc = fmaf(sm_p[d], fc_W[d * FCL + tid], acc);
        g_qT[tid * BB + b] = acc;
    } else if (tid < KD) {
        g_qT[tid * BB + b] = 0.f;   // K padding
    }

    // c = p . fc_b
    float pc = 0.f;
    for (int d = tid; d < DD; d += blockDim.x) pc += sm_p[d] * fc_b[d];
    #pragma unroll
    for (int o = 16; o; o >>= 1) pc += __shfl_down_sync(0xffffffffu, pc, o);
    if ((tid & 31) == 0) sm_red[tid >> 5] = pc;
    __syncthreads();
    if (tid == 0) {
        float t = 0.f;
        #pragma unroll
        for (int w = 0; w < 8; w++) t += sm_red[w];
        g_c[b] = t;
    }
}

// ============================================================
// K1: F features for entity_emb[:NL], stored transposed g_FT[k][n]
//  F[n, ch*39+w] = sum_j E[n, 5w+j] * k4[ch*10+j],  pos=4 kernel
// ============================================================
#define K1R 32
__global__ void k1_feat(const float* __restrict__ entity,
                        const float* __restrict__ fc2_W,
                        const float* __restrict__ fc2_b)
{
    __shared__ float e_sm[K1R][201];
    __shared__ float f_sm[K1R][81];
    __shared__ float k_sm[20];

    const int tid = threadIdx.x;
    const int n0  = blockIdx.x * K1R;

    if (tid < 20) k_sm[tid] = fc2_W[tid * 6 + 4] + fc2_b[tid];
    for (int i = tid; i < K1R * DD; i += 256) {
        const int r = i / DD, c = i % DD;
        const int n = n0 + r;
        e_sm[r][c] = (n < NL) ? entity[(long)n * DD + c] : 0.f;
    }
    __syncthreads();

    const int r = tid >> 3, lane = tid & 7;
    #pragma unroll
    for (int k = 0; k < 10; k++) {
        const int f = lane + 8 * k;
        float acc = 0.f;
        if (f < FCL) {
            const int ch = f / 39, w = f % 39;
            #pragma unroll
            for (int j = 0; j < 10; j++)
                acc = fmaf(e_sm[r][w * 5 + j], k_sm[ch * 10 + j], acc);
        }
        f_sm[r][f] = acc;   // f in [0,80): pads get 0
    }
    __syncthreads();

    // transposed, coalesced writeback: consecutive threads -> consecutive n
    for (int i = tid; i < K1R * KD; i += 256) {
        const int f = i >> 5;          // 0..79
        const int rr = i & 31;
        const int n = n0 + rr;
        if (n < NL) g_FT[f * NLP + n] = f_sm[rr][f];
    }
}

// ============================================================
// K2: ontScores[b, o] = sum_d | s[b,d] - ont[o,d] |
//  tile: 16 b x 96 o per block, 256 threads, 6 outputs/thread
// ============================================================
#define K2_BO 96
__global__ void k2_ont(const float* __restrict__ ont, float* __restrict__ out)
{
    __shared__ float s_sm[16][ODIM];
    __shared__ float o_sm[K2_BO][ODIM + 1];

    const int tid = threadIdx.x;
    const int o0 = blockIdx.x * K2_BO;
    const int b0 = blockIdx.y * 16;

    for (int i = tid; i < 16 * ODIM; i += 256) {
        const int r = i / ODIM, c = i % ODIM;
        s_sm[r][c] = g_s[(b0 + r) * ODIM + c];
    }
    for (int i = tid; i < K2_BO * ODIM; i += 256) {
        const int r = i / ODIM, c = i % ODIM;
        const int o = o0 + r;
        o_sm[r][c] = (o < NO) ? ont[o * ODIM + c] : 0.f;
    }
    __syncthreads();

    const int bi = tid >> 4, oi = tid & 15;
    float acc[6] = {0.f, 0.f, 0.f, 0.f, 0.f, 0.f};
    for (int d = 0; d < ODIM; d++) {
        const float sv = s_sm[bi][d];
        #pragma unroll
        for (int k = 0; k < 6; k++)
            acc[k] += fabsf(sv - o_sm[k * 16 + oi][d]);
    }
    const int b = b0 + bi;
    #pragma unroll
    for (int k = 0; k < 6; k++) {
        const int o = o0 + k * 16 + oi;
        if (o < NO) out[b * NO + o] = acc[k];
    }
}

// ============================================================
// K3: hypeScores[b,n] = q[b] . F[n] + c[b]
//  SGEMM M=256 N=50000 K=80(padded), 128x128 tile, 8x8 per thread
// ============================================================
__global__ void __launch_bounds__(256, 2)
k3_gemm(float* __restrict__ out)
{
    extern __shared__ float smem[];
    float (*qs)[128] = reinterpret_cast<float(*)[128]>(smem);
    float (*fs)[128] = reinterpret_cast<float(*)[128]>(smem + KD * 128);

    const int tid = threadIdx.x;
    const int n0 = blockIdx.x * 128;
    const int m0 = blockIdx.y * 128;

    // load both tiles: [k][m] layout, coalesced global, conflict-free smem
    for (int i = tid; i < KD * 32; i += 256) {
        const int k = i >> 5;
        const int o = (i & 31) << 2;
        const float4 a = *reinterpret_cast<const float4*>(&g_qT[k * BB + m0 + o]);
        *reinterpret_cast<float4*>(&qs[k][o]) = a;
        const float4 f = *reinterpret_cast<const float4*>(&g_FT[k * NLP + n0 + o]);
        *reinterpret_cast<float4*>(&fs[k][o]) = f;
    }
    __syncthreads();

    const int tx = tid & 15, ty = tid >> 4;
    float acc[8][8];
    #pragma unroll
    for (int i = 0; i < 8; i++)
        #pragma unroll
        for (int j = 0; j < 8; j++) acc[i][j] = 0.f;

    #pragma unroll 4
    for (int k = 0; k < KD; k++) {
        float4 a0 = *reinterpret_cast<const float4*>(&qs[k][ty * 8]);
        float4 a1 = *reinterpret_cast<const float4*>(&qs[k][ty * 8 + 4]);
        float4 b0 = *reinterpret_cast<const float4*>(&fs[k][tx * 8]);
        float4 b1 = *reinterpret_cast<const float4*>(&fs[k][tx * 8 + 4]);
        const float av[8] = {a0.x, a0.y, a0.z, a0.w, a1.x, a1.y, a1.z, a1.w};
        const float bv[8] = {b0.x, b0.y, b0.z, b0.w, b1.x, b1.y, b1.z, b1.w};
        #pragma unroll
        for (int i = 0; i < 8; i++)
            #pragma unroll
            for (int j = 0; j < 8; j++)
                acc[i][j] = fmaf(av[i], bv[j], acc[i][j]);
    }

    // epilogue: + c[b], write to out (hype section)
    float* hyp = out + BB * NO;
    #pragma unroll
    for (int i = 0; i < 8; i++) {
        const int b = m0 + ty * 8 + i;
        const float cb = g_c[b];
        const int n = n0 + tx * 8;
        if (n < NL) {
            float4 v0, v1;
            v0.x = acc[i][0] + cb; v0.y = acc[i][1] + cb;
            v0.z = acc[i][2] + cb; v0.w = acc[i][3] + cb;
            v1.x = acc[i][4] + cb; v1.y = acc[i][5] + cb;
            v1.z = acc[i][6] + cb; v1.w = acc[i][7] + cb;
            float* p = hyp + (long)b * NL + n;
            *reinterpret_cast<float4*>(p) = v0;
            if (n + 4 < NL) *reinterpret_cast<float4*>(p + 4) = v1;
        }
    }
}

// ============================================================
// launcher
// ============================================================
extern "C" void kernel_launch(void* const* d_in, const int* in_sizes, int n_in,
                              void* d_out, int out_size)
{
    const int*   rel_idx   = (const int*)  d_in[0];
    const int*   rel2_idx  = (const int*)  d_in[1];
    const int*   user_idx  = (const int*)  d_in[2];
    const int*   hour_idx  = (const int*)  d_in[3];
    const int*   day_idx   = (const int*)  d_in[4];
    const int*   type_idx  = (const int*)  d_in[5];
    // d_in[6] = currentBatchSize (always 256)
    const float* entity    = (const float*)d_in[7];
    const float* ont       = (const float*)d_in[8];
    const float* relation  = (const float*)d_in[9];
    const float* proj_W    = (const float*)d_in[10];
    const float* proj_b    = (const float*)d_in[11];
    const float* pR_W      = (const float*)d_in[12];
    const float* pR_b      = (const float*)d_in[13];
    const float* fc2_W     = (const float*)d_in[14];
    const float* fc2_b     = (const float*)d_in[15];
    const float* fc_W      = (const float*)d_in[16];
    const float* fc_b      = (const float*)d_in[17];
    float* out = (float*)d_out;

    const int k3_smem = 2 * KD * 128 * (int)sizeof(float);  // 80 KB
    cudaFuncSetAttribute(k3_gemm, cudaFuncAttributeMaxDynamicSharedMemorySize, k3_smem);

    // F features (independent of batch work)
    k1_feat<<<(NL + K1R - 1) / K1R, 256>>>(entity, fc2_W, fc2_b);

    // per-batch vectors
    k0_batch<<<BB, 256>>>(rel_idx, rel2_idx, user_idx, hour_idx, day_idx, type_idx,
                          entity, ont, relation, proj_W, proj_b, pR_W, pR_b,
                          fc2_W, fc2_b, fc_W, fc_b);

    // ontology scores
    dim3 g2((NO + K2_BO - 1) / K2_BO, BB / 16);
    k2_ont<<<g2, 256>>>(ont, out);

    // hype scores GEMM
    dim3 g3((NL + 127) / 128, BB / 128);
    k3_gemm<<<g3, 256, k3_smem>>>(out);
}

// round 2
// speedup vs baseline: 1.1310x; 1.1310x over previous
#include <cuda_runtime.h>

// ---------------- problem constants ----------------
#define BB   256      // batch
#define DD   200      // embedding dim
#define ODIM 100      // ontology dim
#define NO   5000     // ontology rows
#define NL   50000    // locations
#define FCL  78       // conv feature length (2*39)
#define KD   80       // padded K
#define NLP  50048    // NL padded to GEMM tile multiple

typedef unsigned long long u64;

// ---------------- device scratch (zero-initialized .bss) ----------------
__device__ float g_s [BB * ODIM];     // typeSub + subRel
__device__ float g_qT[KD * BB];       // q transposed: [k][b]
__device__ float g_c [BB];            // p . fc_b
__device__ float g_FT[KD * NLP];      // F transposed: [k][n], tail stays 0

// ---------------- f32x2 packed helpers ----------------
__device__ __forceinline__ u64 splat2(float x) {
    u64 r; asm("mov.b64 %0,{%1,%1};" : "=l"(r) : "r"(__float_as_uint(x))); return r;
}
__device__ __forceinline__ u64 fma2(u64 a, u64 b, u64 c) {
    u64 d; asm("fma.rn.f32x2 %0,%1,%2,%3;" : "=l"(d) : "l"(a), "l"(b), "l"(c)); return d;
}
__device__ __forceinline__ u64 add2(u64 a, u64 b) {
    u64 d; asm("add.rn.f32x2 %0,%1,%2;" : "=l"(d) : "l"(a), "l"(b)); return d;
}
__device__ __forceinline__ float2 u2f(u64 a) {
    float2 f; f.x = __uint_as_float((unsigned)a); f.y = __uint_as_float((unsigned)(a >> 32)); return f;
}

// ============================================================
// K0: all per-batch work. 1 block per batch element.
// Restructured: stage all conv inputs, share fc_W reads across
// the 4 fc-gemvs, multi-accumulator full-unroll gemvs.
// ============================================================
__global__ void k0_batch(const int* __restrict__ rel_idx,
                         const int* __restrict__ rel2_idx,
                         const int* __restrict__ user_idx,
                         const int* __restrict__ hour_idx,
                         const int* __restrict__ day_idx,
                         const int* __restrict__ type_idx,
                         const float* __restrict__ entity,
                         const float* __restrict__ ont,
                         const float* __restrict__ relation,
                         const float* __restrict__ proj_W,
                         const float* __restrict__ proj_b,
                         const float* __restrict__ pR_W,
                         const float* __restrict__ pR_b,
                         const float* __restrict__ fc2_W,
                         const float* __restrict__ fc2_b,
                         const float* __restrict__ fc_W,
                         const float* __restrict__ fc_b)
{
    const int b   = blockIdx.x;
    const int tid = threadIdx.x;

    __shared__ float sm_rel2[DD];
    __shared__ float sm_ts[ODIM];
    __shared__ float sm_in[4][DD];     // user, day, hour, tt
    __shared__ float sm_k[4][20];      // conv kernels for pos 1,2,3,5
    __shared__ float sm_y[4][80];      // conv outputs (padded)
    __shared__ float sm_p[DD];
    __shared__ float sm_red[8];

    const int i_rel  = rel_idx[b];
    const int i_r2   = rel2_idx[b];
    const int i_type = type_idx[b];

    // ---- stage A: load everything independent ----
    if (tid < DD)   sm_rel2[tid] = relation[i_r2 * DD + tid];
    if (tid < ODIM) sm_ts[tid]   = ont[i_type * ODIM + tid];
    {
        int idx0 = user_idx[b], idx1 = day_idx[b], idx2 = hour_idx[b];
        for (int i = tid; i < 3 * DD; i += 256) {
            const int s = i / DD, c = i % DD;
            const int row = (s == 0) ? idx0 : (s == 1) ? idx1 : idx2;
            sm_in[s][c] = entity[(long)row * DD + c];
        }
    }
    if (tid < 80) {
        const int s = tid / 20, w = tid % 20;
        const int poss[4] = {1, 2, 3, 5};
        sm_k[s][w] = fc2_W[w * 6 + poss[s]] + fc2_b[w];
    }
    __syncthreads();

    // ---- stage B: subRel -> g_s ; tt -> sm_in[3] ----
    if (tid < ODIM) {
        const float* w = pR_W + tid * DD;
        float a0 = 0.f, a1 = 0.f, a2 = 0.f, a3 = 0.f;
        #pragma unroll
        for (int d = 0; d < DD; d += 4) {
            a0 = fmaf(sm_rel2[d],     w[d],     a0);
            a1 = fmaf(sm_rel2[d + 1], w[d + 1], a1);
            a2 = fmaf(sm_rel2[d + 2], w[d + 2], a2);
            a3 = fmaf(sm_rel2[d + 3], w[d + 3], a3);
        }
        const float v = (a0 + a1) + (a2 + a3) + pR_b[tid];
        g_s[b * ODIM + tid] = sm_ts[tid] + fmaxf(v, 0.f);
    }
    if (tid < DD) {
        const float* w = proj_W + tid * ODIM;
        float a0 = 0.f, a1 = 0.f, a2 = 0.f, a3 = 0.f;
        #pragma unroll
        for (int i = 0; i < ODIM; i += 4) {
            a0 = fmaf(sm_ts[i],     w[i],     a0);
            a1 = fmaf(sm_ts[i + 1], w[i + 1], a1);
            a2 = fmaf(sm_ts[i + 2], w[i + 2], a2);
            a3 = fmaf(sm_ts[i + 3], w[i + 3], a3);
        }
        sm_in[3][tid] = fmaxf((a0 + a1) + (a2 + a3) + proj_b[tid], 0.f);
    }
    __syncthreads();

    // ---- stage C: 4 convs in parallel (4 x 78 outputs) ----
    for (int i = tid; i < 4 * 80; i += 256) {
        const int s = i / 80, f = i % 80;
        float acc = 0.f;
        if (f < FCL) {
            const int ch = f / 39, w = f % 39;
            #pragma unroll
            for (int j = 0; j < 10; j++)
                acc = fmaf(sm_in[s][w * 5 + j], sm_k[s][ch * 10 + j], acc);
        }
        sm_y[s][f] = acc;
    }
    __syncthreads();

    // ---- stage D: fused 4-way fc gemv + product ----
    if (tid < DD) {
        const float* w = fc_W + tid * FCL;
        const float bia = fc_b[tid];
        float au = bia, ad = bia, ah = bia, at = bia;
        #pragma unroll
        for (int f = 0; f < FCL; f++) {
            const float wv = w[f];
            au = fmaf(sm_y[0][f], wv, au);
            ad = fmaf(sm_y[1][f], wv, ad);
            ah = fmaf(sm_y[2][f], wv, ah);
            at = fmaf(sm_y[3][f], wv, at);
        }
        const float rel = relation[i_rel * DD + tid];
        sm_p[tid] = rel * au * ad * ah * at;
    }
    __syncthreads();

    // ---- stage E: q = p @ fc_W (transposed store) ; c = p . fc_b ----
    if (tid < FCL) {
        float a0 = 0.f, a1 = 0.f, a2 = 0.f, a3 = 0.f;
        #pragma unroll
        for (int d = 0; d < DD; d += 4) {
            a0 = fmaf(sm_p[d],     fc_W[(d)     * FCL + tid], a0);
            a1 = fmaf(sm_p[d + 1], fc_W[(d + 1) * FCL + tid], a1);
            a2 = fmaf(sm_p[d + 2], fc_W[(d + 2) * FCL + tid], a2);
            a3 = fmaf(sm_p[d + 3], fc_W[(d + 3) * FCL + tid], a3);
        }
        g_qT[tid * BB + b] = (a0 + a1) + (a2 + a3);
    } else if (tid < KD) {
        g_qT[tid * BB + b] = 0.f;
    }

    float pc = 0.f;
    for (int d = tid; d < DD; d += 256) pc += sm_p[d] * fc_b[d];
    #pragma unroll
    for (int o = 16; o; o >>= 1) pc += __shfl_down_sync(0xffffffffu, pc, o);
    if ((tid & 31) == 0) sm_red[tid >> 5] = pc;
    __syncthreads();
    if (tid == 0) {
        float t = 0.f;
        #pragma unroll
        for (int w = 0; w < 8; w++) t += sm_red[w];
        g_c[b] = t;
    }
}

// ============================================================
// K1: F features for entity_emb[:NL], transposed g_FT[k][n]
// float4 global loads.
// ============================================================
#define K1R 32
__global__ void k1_feat(const float* __restrict__ entity,
                        const float* __restrict__ fc2_W,
                        const float* __restrict__ fc2_b)
{
    __shared__ float e_sm[K1R][204];
    __shared__ float f_sm[K1R][80];
    __shared__ float k_sm[20];

    const int tid = threadIdx.x;
    const int n0  = blockIdx.x * K1R;

    if (tid < 20) k_sm[tid] = fc2_W[tid * 6 + 4] + fc2_b[tid];
    for (int i = tid; i < K1R * 50; i += 256) {
        const int r = i / 50, c4 = i % 50;
        const int n = n0 + r;
        float4 v = make_float4(0.f, 0.f, 0.f, 0.f);
        if (n < NL)
            v = *reinterpret_cast<const float4*>(entity + (long)n * DD + c4 * 4);
        *reinterpret_cast<float4*>(&e_sm[r][c4 * 4]) = v;
    }
    __syncthreads();

    const int r = tid >> 3, lane = tid & 7;
    #pragma unroll
    for (int k = 0; k < 10; k++) {
        const int f = lane + 8 * k;
        float acc = 0.f;
        if (f < FCL) {
            const int ch = f / 39, w = f % 39;
            #pragma unroll
            for (int j = 0; j < 10; j++)
                acc = fmaf(e_sm[r][w * 5 + j], k_sm[ch * 10 + j], acc);
        }
        f_sm[r][f] = acc;
    }
    __syncthreads();

    for (int i = tid; i < K1R * KD; i += 256) {
        const int f = i >> 5;
        const int rr = i & 31;
        const int n = n0 + rr;
        if (n < NL) g_FT[f * NLP + n] = f_sm[rr][f];
    }
}

// ============================================================
// K2: ontScores[b,o] = sum_d |s[b,d] - ont[o,d]|
//  32b x 128o tile, 2b x 8o per thread, packed f32x2 along d.
//  ont stored negated -> add2 + and-abs + add2.
// ============================================================
#define K2SD 102   // padded row stride (even => 8B aligned rows)
__global__ void k2_ont(const float* __restrict__ ont, float* __restrict__ out)
{
    __shared__ float o_sm[128][K2SD];   // negated ontology rows
    __shared__ float s_sm[32][K2SD];

    const int tid = threadIdx.x;
    const int o0 = blockIdx.x * 128;
    const int b0 = blockIdx.y * 32;

    for (int i = tid; i < 128 * ODIM; i += 256) {
        const int r = i / ODIM, c = i % ODIM;
        const int o = o0 + r;
        o_sm[r][c] = (o < NO) ? -ont[o * ODIM + c] : 0.f;
    }
    for (int i = tid; i < 32 * ODIM; i += 256) {
        const int r = i / ODIM, c = i % ODIM;
        s_sm[r][c] = g_s[(b0 + r) * ODIM + c];
    }
    __syncthreads();

    const int tx = tid & 15;          // o-lane
    const int ty = tid >> 4;          // b-pair: b = b0 + 2*ty + {0,1}
    const int bb = ty * 2;

    const u64 AMASK = 0x7FFFFFFF7FFFFFFFULL;
    u64 acc[2][8];
    #pragma unroll
    for (int i = 0; i < 2; i++)
        #pragma unroll
        for (int j = 0; j < 8; j++) acc[i][j] = 0ULL;

    #pragma unroll 2
    for (int d = 0; d < ODIM; d += 2) {
        const u64 s0 = *reinterpret_cast<const u64*>(&s_sm[bb][d]);
        const u64 s1 = *reinterpret_cast<const u64*>(&s_sm[bb + 1][d]);
        #pragma unroll
        for (int j = 0; j < 8; j++) {
            const u64 ov = *reinterpret_cast<const u64*>(&o_sm[tx + 16 * j][d]);
            acc[0][j] = add2(acc[0][j], add2(s0, ov) & AMASK);
            acc[1][j] = add2(acc[1][j], add2(s1, ov) & AMASK);
        }
    }

    #pragma unroll
    for (int i = 0; i < 2; i++) {
        const int b = b0 + bb + i;
        #pragma unroll
        for (int j = 0; j < 8; j++) {
            const int o = o0 + tx + 16 * j;
            if (o < NO) {
                const float2 f = u2f(acc[i][j]);
                out[b * NO + o] = f.x + f.y;
            }
        }
    }
}

// ============================================================
// K3: hypeScores[b,n] = q[b].F[n] + c[b]
//  SGEMM M=256 N=50048 K=80, 128x128 tile, 8x8/thread,
//  packed f32x2 FFMA2 inner loop.
// ============================================================
__global__ void __launch_bounds__(256, 2)
k3_gemm(float* __restrict__ out)
{
    extern __shared__ float smem[];
    float (*qs)[128] = reinterpret_cast<float(*)[128]>(smem);
    float (*fs)[128] = reinterpret_cast<float(*)[128]>(smem + KD * 128);

    const int tid = threadIdx.x;
    const int n0 = blockIdx.x * 128;
    const int m0 = blockIdx.y * 128;

    for (int i = tid; i < KD * 32; i += 256) {
        const int k = i >> 5;
        const int o = (i & 31) << 2;
        *reinterpret_cast<float4*>(&qs[k][o]) =
            *reinterpret_cast<const float4*>(&g_qT[k * BB + m0 + o]);
        *reinterpret_cast<float4*>(&fs[k][o]) =
            *reinterpret_cast<const float4*>(&g_FT[k * NLP + n0 + o]);
    }
    __syncthreads();

    const int tx = tid & 15, ty = tid >> 4;

    u64 acc[8][4];
    #pragma unroll
    for (int i = 0; i < 8; i++)
        #pragma unroll
        for (int j = 0; j < 4; j++) acc[i][j] = 0ULL;

    #pragma unroll 4
    for (int k = 0; k < KD; k++) {
        const float4 a0 = *reinterpret_cast<const float4*>(&qs[k][ty * 8]);
        const float4 a1 = *reinterpret_cast<const float4*>(&qs[k][ty * 8 + 4]);
        const ulonglong2 b0 = *reinterpret_cast<const ulonglong2*>(&fs[k][tx * 8]);
        const ulonglong2 b1 = *reinterpret_cast<const ulonglong2*>(&fs[k][tx * 8 + 4]);
        u64 bp[4] = {b0.x, b0.y, b1.x, b1.y};
        u64 as[8];
        as[0] = splat2(a0.x); as[1] = splat2(a0.y);
        as[2] = splat2(a0.z); as[3] = splat2(a0.w);
        as[4] = splat2(a1.x); as[5] = splat2(a1.y);
        as[6] = splat2(a1.z); as[7] = splat2(a1.w);
        #pragma unroll
        for (int i = 0; i < 8; i++)
            #pragma unroll
            for (int j = 0; j < 4; j++)
                acc[i][j] = fma2(as[i], bp[j], acc[i][j]);
    }

    // epilogue: + c[b]; guard: NL % 8 == 0, so n<NL covers all 8 lanes
    float* hyp = out + BB * NO;
    const int n = n0 + tx * 8;
    if (n < NL) {
        #pragma unroll
        for (int i = 0; i < 8; i++) {
            const int b = m0 + ty * 8 + i;
            const float cb = g_c[b];
            const float2 p0 = u2f(acc[i][0]);
            const float2 p1 = u2f(acc[i][1]);
            const float2 p2 = u2f(acc[i][2]);
            const float2 p3 = u2f(acc[i][3]);
            float4 v0, v1;
            v0.x = p0.x + cb; v0.y = p0.y + cb;
            v0.z = p1.x + cb; v0.w = p1.y + cb;
            v1.x = p2.x + cb; v1.y = p2.y + cb;
            v1.z = p3.x + cb; v1.w = p3.y + cb;
            float* p = hyp + (long)b * NL + n;
            *reinterpret_cast<float4*>(p)     = v0;
            *reinterpret_cast<float4*>(p + 4) = v1;
        }
    }
}

// ============================================================
// launcher
// ============================================================
extern "C" void kernel_launch(void* const* d_in, const int* in_sizes, int n_in,
                              void* d_out, int out_size)
{
    const int*   rel_idx   = (const int*)  d_in[0];
    const int*   rel2_idx  = (const int*)  d_in[1];
    const int*   user_idx  = (const int*)  d_in[2];
    const int*   hour_idx  = (const int*)  d_in[3];
    const int*   day_idx   = (const int*)  d_in[4];
    const int*   type_idx  = (const int*)  d_in[5];
    // d_in[6] = currentBatchSize (always 256)
    const float* entity    = (const float*)d_in[7];
    const float* ont       = (const float*)d_in[8];
    const float* relation  = (const float*)d_in[9];
    const float* proj_W    = (const float*)d_in[10];
    const float* proj_b    = (const float*)d_in[11];
    const float* pR_W      = (const float*)d_in[12];
    const float* pR_b      = (const float*)d_in[13];
    const float* fc2_W     = (const float*)d_in[14];
    const float* fc2_b     = (const float*)d_in[15];
    const float* fc_W      = (const float*)d_in[16];
    const float* fc_b      = (const float*)d_in[17];
    float* out = (float*)d_out;

    const int k3_smem = 2 * KD * 128 * (int)sizeof(float);  // 80 KB
    cudaFuncSetAttribute(k3_gemm, cudaFuncAttributeMaxDynamicSharedMemorySize, k3_smem);

    k1_feat<<<(NL + K1R - 1) / K1R, 256>>>(entity, fc2_W, fc2_b);

    k0_batch<<<BB, 256>>>(rel_idx, rel2_idx, user_idx, hour_idx, day_idx, type_idx,
                          entity, ont, relation, proj_W, proj_b, pR_W, pR_b,
                          fc2_W, fc2_b, fc_W, fc_b);

    dim3 g2((NO + 127) / 128, BB / 32);
    k2_ont<<<g2, 256>>>(ont, out);

    dim3 g3((NL + 127) / 128, BB / 128);
    k3_gemm<<<g3, 256, k3_smem>>>(out);
}